// round 15
// baseline (speedup 1.0000x reference)
#include <cuda_runtime.h>
#include <cstdint>

#define B_    16
#define NNODE 7
#define HID_  256
#define C_    256
#define P_    (96 * 96)       // 9216
#define P4_   (P_ / 4)        // 2304 float4 per row
#define CTILE 32
#define NCT   (C_ / CTILE)    // 8
#define NCOMP (B_ * NCT)      // 128 compute blocks
#define NROW  (B_ * C_)       // 4096 fill rows

// Scratch (zero-init at module load; flags/counters restored to 0 in-launch).
__device__ float    g_v[NROW];
__device__ unsigned g_flag[NCOMP];
__device__ unsigned g_cnt[NCOMP];

__device__ __forceinline__ float ldcg_f(const float* p) {
    float v;
    asm volatile("ld.global.cg.f32 %0, [%1];" : "=f"(v) : "l"(p));
    return v;
}

// ───────────── Fused kernel: blocks [0,128) compute, [128,4224) fill ────────
__global__ __launch_bounds__(256)
void g2f_fused_kernel(const float* __restrict__ x,    // (B, NNODE, HID)
                      const float* __restrict__ nfh,  // (HID)
                      const float* __restrict__ W,    // (HID, C)
                      float* __restrict__ out)        // (B, C, P)
{
    const int bid = blockIdx.x;
    const int t   = threadIdx.x;

    if (bid < NCOMP) {
        // ───── compute block: v[b, c0..c0+31] ─────
        const int b  = bid / NCT;
        const int c0 = (bid % NCT) * CTILE;
        const int lane = t & 31;
        const int warp = t >> 5;

        __shared__ float wsum[8][NNODE];
        __shared__ float s_hid[NNODE];
        __shared__ float y_sh[HID_];
        __shared__ float part[8][CTILE];

        // W loads first: DRAM latency overlaps the phase-1 chain.
        const int h0 = warp * 32;
        float wv[32];
#pragma unroll
        for (int hh = 0; hh < 32; hh++)
            wv[hh] = W[(h0 + hh) * C_ + c0 + lane];

        const float* xb = x + (size_t)b * NNODE * HID_;
        float xh[NNODE];
#pragma unroll
        for (int n = 0; n < NNODE; n++) xh[n] = xb[n * HID_ + t];
        const float nf = nfh[t];

        float p[NNODE];
#pragma unroll
        for (int n = 0; n < NNODE; n++) p[n] = xh[n] * nf;
#pragma unroll
        for (int off = 16; off > 0; off >>= 1)
#pragma unroll
            for (int n = 0; n < NNODE; n++)
                p[n] += __shfl_down_sync(0xFFFFFFFFu, p[n], off);
        if (lane == 0)
#pragma unroll
            for (int n = 0; n < NNODE; n++) wsum[warp][n] = p[n];
        __syncthreads();
        if (t < NNODE) {
            float s = 0.f;
#pragma unroll
            for (int w = 0; w < 8; w++) s += wsum[w][t];
            s_hid[t] = s;
        }
        __syncthreads();

        float m = s_hid[0];
#pragma unroll
        for (int n = 1; n < NNODE; n++) m = fmaxf(m, s_hid[n]);
        float a[NNODE]; float esum = 0.f;
#pragma unroll
        for (int n = 0; n < NNODE; n++) { a[n] = __expf(s_hid[n] - m); esum += a[n]; }
        const float inv = 1.0f / esum;

        float y = 0.f;
#pragma unroll
        for (int n = 0; n < NNODE; n++) y = fmaf(a[n] * inv, xh[n], y);
        y_sh[t] = y;
        __syncthreads();

        float acc = 0.f;
#pragma unroll
        for (int hh = 0; hh < 32; hh++)
            acc = fmaf(y_sh[h0 + hh], wv[hh], acc);
        part[warp][lane] = acc;
        __syncthreads();

        if (warp == 0) {
            float v = 0.f;
#pragma unroll
            for (int w = 0; w < 8; w++) v += part[w][lane];
            g_v[b * C_ + c0 + lane] = fmaxf(v, 0.0f);
        }
        __syncthreads();
        if (t == 0) {
            __threadfence();                    // release g_v
            atomicExch(&g_flag[bid], 1u);
        }
    } else {
        // ───── fill block: one (b,c) row ─────
        const int row = bid - NCOMP;            // b*C + c
        const int fi  = row >> 5;               // flag index (32 rows/flag)

        if (t == 0) {
            while (atomicAdd(&g_flag[fi], 0u) == 0u) { }
            __threadfence();                    // acquire
        }
        __syncthreads();

        const float v = ldcg_f(&g_v[row]);      // L2 read (skip L1)
        const float4 val = make_float4(v, v, v, v);
        float4* o = reinterpret_cast<float4*>(out + (size_t)row * P_);
#pragma unroll
        for (int i = 0; i < P4_ / 256; i++)     // 9 streaming STG.128
            __stcs(&o[i * 256 + t], val);

        // Last of the 32 consumer blocks restores flag/counter to 0 so the
        // next graph replay (stream-serialized) starts clean.
        if (t == 0) {
            unsigned r = atomicAdd(&g_cnt[fi], 1u);
            if (r == 31u) {
                g_cnt[fi] = 0u;
                atomicExch(&g_flag[fi], 0u);
            }
        }
    }
}

extern "C" void kernel_launch(void* const* d_in, const int* in_sizes, int n_in,
                              void* d_out, int out_size)
{
    const float* x   = (const float*)d_in[0];  // (1,16,7,256)
    // d_in[1] res_feature, d_in[2] node_fea_for_res: cancel in softmax — unused
    const float* nfh = (const float*)d_in[3];  // (256,1)
    const float* W   = (const float*)d_in[4];  // (256,256)
    float* out = (float*)d_out;

    g2f_fused_kernel<<<NCOMP + NROW, 256>>>(x, nfh, W, out);
}